// round 6
// baseline (speedup 1.0000x reference)
#include <cuda_runtime.h>
#include <math.h>
#include <stdint.h>

#define B_  2
#define L_  2048
#define D_  1024
#define H_  16
#define DH_ 64
#define M_  (B_*L_)   // 4096 rows

typedef unsigned long long ull;

// Scratch (allocation-free rule): Q, K, V, attention output. 16 MB each.
__device__ float g_Q [(size_t)M_*D_];
__device__ float g_K [(size_t)M_*D_];
__device__ float g_V [(size_t)M_*D_];
__device__ float g_Ao[(size_t)M_*D_];

// ---------------------------------------------------------------------------
// helpers: tf32 split, mma, packed f32x2
// ---------------------------------------------------------------------------
__device__ __forceinline__ float2 split_tf32(float x) {
    float h, l;
    asm("cvt.rna.tf32.f32 %0, %1;" : "=f"(h) : "f"(x));
    float r = x - h;
    asm("cvt.rna.tf32.f32 %0, %1;" : "=f"(l) : "f"(r));
    return make_float2(h, l);
}

__device__ __forceinline__ void mma_tf32(float* d,
    uint32_t a0, uint32_t a1, uint32_t a2, uint32_t a3,
    uint32_t b0, uint32_t b1)
{
    asm volatile(
        "mma.sync.aligned.m16n8k8.row.col.f32.tf32.tf32.f32 "
        "{%0,%1,%2,%3}, {%4,%5,%6,%7}, {%8,%9}, {%0,%1,%2,%3};\n"
        : "+f"(d[0]), "+f"(d[1]), "+f"(d[2]), "+f"(d[3])
        : "r"(a0), "r"(a1), "r"(a2), "r"(a3), "r"(b0), "r"(b1));
}

__device__ __forceinline__ ull pk2(float lo, float hi) {
    ull r; asm("mov.b64 %0, {%1,%2};" : "=l"(r) : "f"(lo), "f"(hi)); return r;
}
__device__ __forceinline__ void upk2(ull v, float& lo, float& hi) {
    asm("mov.b64 {%0,%1}, %2;" : "=f"(lo), "=f"(hi) : "l"(v));
}
__device__ __forceinline__ void fma2(ull& d, ull a, ull b) {
    asm("fma.rn.f32x2 %0, %1, %2, %0;" : "+l"(d) : "l"(a), "l"(b));
}
__device__ __forceinline__ ull mul2(ull a, ull b) {
    ull r; asm("mul.rn.f32x2 %0, %1, %2;" : "=l"(r) : "l"(a), "l"(b)); return r;
}

// ---------------------------------------------------------------------------
// C[M,N] = A[M,K] @ W[N,K]^T  via tf32 tensor-core mma with 3-product split.
// Block tile 128x64, BK=16, 256 threads = 8 warps (4 m x 2 n), warp tile 32x32.
// Smem holds {hi,lo} interleaved as float2.
// ---------------------------------------------------------------------------
#define BM 128
#define BN 64
#define BK 16

__global__ void __launch_bounds__(256)
gemm_tf32(const float* __restrict__ A, const float* __restrict__ W,
          float* __restrict__ C, int M, int N, int K)
{
    __shared__ float2 As[BM][BK + 1];   // stride 17 float2 (8B units)
    __shared__ float2 Ws[BN][BK + 1];

    const int tid  = threadIdx.x;
    const int lane = tid & 31, wid = tid >> 5;
    const int g    = lane >> 2, tg = lane & 3;     // groupID, threadID-in-group
    const int wm   = wid & 3,  wn = wid >> 2;      // warp grid 4 x 2
    const int m0   = blockIdx.y * BM, n0 = blockIdx.x * BN;

    float acc[2][4][4];
    #pragma unroll
    for (int i = 0; i < 2; i++)
        #pragma unroll
        for (int j = 0; j < 4; j++)
            #pragma unroll
            for (int r = 0; r < 4; r++) acc[i][j][r] = 0.f;

    for (int k0 = 0; k0 < K; k0 += BK) {
        __syncthreads();
        // ---- load + split A tile (128x16 floats = 512 float4, 2 per thread)
        #pragma unroll
        for (int t = tid; t < 512; t += 256) {
            int r = t >> 2, kq = (t & 3) * 4;
            float4 v = *(const float4*)(A + (size_t)(m0 + r) * K + k0 + kq);
            As[r][kq + 0] = split_tf32(v.x);
            As[r][kq + 1] = split_tf32(v.y);
            As[r][kq + 2] = split_tf32(v.z);
            As[r][kq + 3] = split_tf32(v.w);
        }
        // ---- load + split W tile (64x16 floats = 256 float4, 1 per thread)
        {
            int r = tid >> 2, kq = (tid & 3) * 4;
            float4 v = *(const float4*)(W + (size_t)(n0 + r) * K + k0 + kq);
            Ws[r][kq + 0] = split_tf32(v.x);
            Ws[r][kq + 1] = split_tf32(v.y);
            Ws[r][kq + 2] = split_tf32(v.z);
            Ws[r][kq + 3] = split_tf32(v.w);
        }
        __syncthreads();

        #pragma unroll
        for (int ks = 0; ks < 2; ks++) {
            const int kb = ks * 8;
            // A fragments (hi,lo as float2)
            float2 a0[2], a1[2], a2[2], a3[2];
            #pragma unroll
            for (int i = 0; i < 2; i++) {
                int mr = wm * 32 + i * 16;
                a0[i] = As[mr + g    ][kb + tg    ];
                a1[i] = As[mr + g + 8][kb + tg    ];
                a2[i] = As[mr + g    ][kb + tg + 4];
                a3[i] = As[mr + g + 8][kb + tg + 4];
            }
            // B fragments
            float2 b0[4], b1[4];
            #pragma unroll
            for (int j = 0; j < 4; j++) {
                int nr = wn * 32 + j * 8;
                b0[j] = Ws[nr + g][kb + tg    ];
                b1[j] = Ws[nr + g][kb + tg + 4];
            }
            #pragma unroll
            for (int i = 0; i < 2; i++) {
                #pragma unroll
                for (int j = 0; j < 4; j++) {
                    // hi*hi
                    mma_tf32(acc[i][j],
                        __float_as_uint(a0[i].x), __float_as_uint(a1[i].x),
                        __float_as_uint(a2[i].x), __float_as_uint(a3[i].x),
                        __float_as_uint(b0[j].x), __float_as_uint(b1[j].x));
                    // hi*lo
                    mma_tf32(acc[i][j],
                        __float_as_uint(a0[i].x), __float_as_uint(a1[i].x),
                        __float_as_uint(a2[i].x), __float_as_uint(a3[i].x),
                        __float_as_uint(b0[j].y), __float_as_uint(b1[j].y));
                    // lo*hi
                    mma_tf32(acc[i][j],
                        __float_as_uint(a0[i].y), __float_as_uint(a1[i].y),
                        __float_as_uint(a2[i].y), __float_as_uint(a3[i].y),
                        __float_as_uint(b0[j].x), __float_as_uint(b1[j].x));
                }
            }
        }
    }

    // ---- epilogue: c0,c1 -> (row g, cols 2tg, 2tg+1); c2,c3 -> row g+8
    #pragma unroll
    for (int i = 0; i < 2; i++) {
        #pragma unroll
        for (int j = 0; j < 4; j++) {
            int r = m0 + wm * 32 + i * 16 + g;
            int c = n0 + wn * 32 + j * 8 + tg * 2;
            *(float2*)(C + (size_t)r * N + c)       = make_float2(acc[i][j][0], acc[i][j][1]);
            *(float2*)(C + (size_t)(r + 8) * N + c) = make_float2(acc[i][j][2], acc[i][j][3]);
        }
    }
}

// ---------------------------------------------------------------------------
// Causal flash attention, 64-query tile per block per (b,h).
// Packed f32x2 FMA everywhere; Q/K transposed in smem so the inner loops are
// LDS.128-fed. V reuses the K buffer. qb order reversed (big tiles first).
// ---------------------------------------------------------------------------
#define AT_STR 68    // sQT / sKT / sV stride (floats), %4==0 for LDS.128
#define P_STR  65

__global__ void __launch_bounds__(256)
attn_kernel()
{
    extern __shared__ float sm[];
    float* sQT = sm;                   // [64][AT_STR]  (d-major: [d][row])
    float* sKT = sm + 64 * AT_STR;     // [64][AT_STR]  (d-major: [d][kv])
    float* sP  = sm + 2 * 64 * AT_STR; // [64][P_STR]   (row-major)
    float* sV  = sKT;                  // V overlays K buffer, [k][dim], stride AT_STR

    const int tx  = threadIdx.x, ty = threadIdx.y;
    const int tid = ty * 16 + tx;
    const int qb  = (L_ / 64 - 1) - blockIdx.x;   // big tiles first
    const int b   = blockIdx.y >> 4;
    const int h   = blockIdx.y & 15;

    const size_t base = (size_t)b * L_ * D_ + (size_t)h * DH_;
    const float* Qp = g_Q + base;
    const float* Kp = g_K + base;
    const float* Vp = g_V + base;

    // Load the 64x64 Q tile, transposed into sQT[d][row]
    for (int idx = tid; idx < 64 * 64; idx += 256) {
        int r = idx >> 6, c = idx & 63;
        sQT[c * AT_STR + r] = Qp[(size_t)(qb * 64 + r) * D_ + c];
    }

    float Mx[4], Ls[4];
    ull accO[4][2];
    #pragma unroll
    for (int i = 0; i < 4; i++) {
        Mx[i] = -INFINITY; Ls[i] = 0.f;
        accO[i][0] = 0ull; accO[i][1] = 0ull;
    }

    for (int kb = 0; kb <= qb; kb++) {
        __syncthreads();  // prev iter done reading sV/sP (also orders Q store)
        // Load K tile transposed into sKT[d][kv]
        for (int idx = tid; idx < 64 * 64; idx += 256) {
            int r = idx >> 6, c = idx & 63;
            sKT[c * AT_STR + r] = Kp[(size_t)(kb * 64 + r) * D_ + c];
        }
        __syncthreads();

        // S = Q K^T : packed over kv-column pairs
        ull accS[4][2];
        #pragma unroll
        for (int i = 0; i < 4; i++) { accS[i][0] = 0ull; accS[i][1] = 0ull; }

        #pragma unroll 4
        for (int d = 0; d < 64; d++) {
            const float4 aq = *(const float4*)(sQT + d * AT_STR + ty * 4);
            const float4 kq = *(const float4*)(sKT + d * AT_STR + tx * 4);
            const ull k01 = pk2(kq.x, kq.y);
            const ull k23 = pk2(kq.z, kq.w);
            ull aa;
            aa = pk2(aq.x, aq.x); fma2(accS[0][0], aa, k01); fma2(accS[0][1], aa, k23);
            aa = pk2(aq.y, aq.y); fma2(accS[1][0], aa, k01); fma2(accS[1][1], aa, k23);
            aa = pk2(aq.z, aq.z); fma2(accS[2][0], aa, k01); fma2(accS[2][1], aa, k23);
            aa = pk2(aq.w, aq.w); fma2(accS[3][0], aa, k01); fma2(accS[3][1], aa, k23);
        }

        float S[4][4];
        #pragma unroll
        for (int i = 0; i < 4; i++) {
            upk2(accS[i][0], S[i][0], S[i][1]);
            upk2(accS[i][1], S[i][2], S[i][3]);
        }

        const bool diag = (kb == qb);
        #pragma unroll
        for (int i = 0; i < 4; i++) {
            #pragma unroll
            for (int j = 0; j < 4; j++) {
                float sv = S[i][j] * 0.125f;     // 1/sqrt(64)
                if (diag && (tx * 4 + j) > (ty * 4 + i)) sv = -INFINITY;
                S[i][j] = sv;
            }
        }

        // Online softmax per owned row (reduction across the 16 tx lanes)
        #pragma unroll
        for (int i = 0; i < 4; i++) {
            float mx = fmaxf(fmaxf(S[i][0], S[i][1]), fmaxf(S[i][2], S[i][3]));
            #pragma unroll
            for (int o = 8; o > 0; o >>= 1)
                mx = fmaxf(mx, __shfl_xor_sync(0xffffffffu, mx, o));
            float newM = fmaxf(Mx[i], mx);
            float corr = __expf(Mx[i] - newM);   // first tile: exp(-inf)=0
            Mx[i] = newM;
            Ls[i] *= corr;
            const ull cc = pk2(corr, corr);
            accO[i][0] = mul2(accO[i][0], cc);
            accO[i][1] = mul2(accO[i][1], cc);

            float P[4], rs = 0.f;
            #pragma unroll
            for (int j = 0; j < 4; j++) {
                P[j] = __expf(S[i][j] - newM);   // masked -> 0
                rs += P[j];
            }
            #pragma unroll
            for (int o = 8; o > 0; o >>= 1)
                rs += __shfl_xor_sync(0xffffffffu, rs, o);
            Ls[i] += rs;
            #pragma unroll
            for (int j = 0; j < 4; j++)
                sP[(ty * 4 + i) * P_STR + tx * 4 + j] = P[j];
        }
        __syncthreads();  // sP written; all sKT reads done

        // Load V tile (row-major [k][dim], overlays K buffer)
        for (int idx = tid; idx < 64 * 64; idx += 256) {
            int r = idx >> 6, c = idx & 63;
            sV[r * AT_STR + c] = Vp[(size_t)(kb * 64 + r) * D_ + c];
        }
        __syncthreads();

        // O += P @ V : packed over output-dim pairs
        #pragma unroll 4
        for (int k = 0; k < 64; k++) {
            const ull v01 = *(const ull*)(sV + k * AT_STR + tx * 4);
            const ull v23 = *(const ull*)(sV + k * AT_STR + tx * 4 + 2);
            #pragma unroll
            for (int i = 0; i < 4; i++) {
                const float p = sP[(ty * 4 + i) * P_STR + k];
                const ull pp = pk2(p, p);
                fma2(accO[i][0], pp, v01);
                fma2(accO[i][1], pp, v23);
            }
        }
    }

    // Epilogue: normalize + write (float4, coalesced)
    float* Op = g_Ao + base;
    #pragma unroll
    for (int i = 0; i < 4; i++) {
        float o0, o1, o2, o3;
        upk2(accO[i][0], o0, o1);
        upk2(accO[i][1], o2, o3);
        float inv = 1.f / Ls[i];
        float4 o4 = make_float4(o0 * inv, o1 * inv, o2 * inv, o3 * inv);
        *(float4*)(Op + (size_t)(qb * 64 + ty * 4 + i) * D_ + tx * 4) = o4;
    }
}

// ---------------------------------------------------------------------------
extern "C" void kernel_launch(void* const* d_in, const int* in_sizes, int n_in,
                              void* d_out, int out_size)
{
    const float* x  = (const float*)d_in[0];
    // d_in[1] = mask (int32 tril) — causality applied analytically
    const float* Wq = (const float*)d_in[2];
    const float* Wk = (const float*)d_in[3];
    const float* Wv = (const float*)d_in[4];
    const float* Wo = (const float*)d_in[5];
    float* out = (float*)d_out;

    void *pQ, *pK, *pV, *pA;
    cudaGetSymbolAddress(&pQ, g_Q);
    cudaGetSymbolAddress(&pK, g_K);
    cudaGetSymbolAddress(&pV, g_V);
    cudaGetSymbolAddress(&pA, g_Ao);

    dim3 ggrd(D_ / BN, M_ / BM);      // (16, 32)
    gemm_tf32<<<ggrd, 256>>>(x, Wq, (float*)pQ, M_, D_, D_);
    gemm_tf32<<<ggrd, 256>>>(x, Wk, (float*)pK, M_, D_, D_);
    gemm_tf32<<<ggrd, 256>>>(x, Wv, (float*)pV, M_, D_, D_);

    const int smem = (2 * 64 * AT_STR + 64 * P_STR) * (int)sizeof(float); // 51456 B
    cudaFuncSetAttribute(attn_kernel,
                         cudaFuncAttributeMaxDynamicSharedMemorySize, smem);
    attn_kernel<<<dim3(L_ / 64, B_ * H_), dim3(16, 16), smem>>>();

    gemm_tf32<<<ggrd, 256>>>((const float*)pA, Wo, out, M_, D_, D_);
}

// round 9
// speedup vs baseline: 1.3373x; 1.3373x over previous
#include <cuda_runtime.h>
#include <math.h>
#include <stdint.h>

#define B_  2
#define L_  2048
#define D_  1024
#define H_  16
#define DH_ 64
#define M_  (B_*L_)   // 4096 rows

typedef unsigned long long ull;

// Scratch (allocation-free rule): Q, K, V, attention output. 16 MB each.
__device__ float g_Q [(size_t)M_*D_];
__device__ float g_K [(size_t)M_*D_];
__device__ float g_V [(size_t)M_*D_];
__device__ float g_Ao[(size_t)M_*D_];

// ---------------------------------------------------------------------------
// packed f32x2 helpers (FFMA2: 2 fp32 MACs per FMA-pipe slot, baseline ISA)
// ---------------------------------------------------------------------------
__device__ __forceinline__ ull pk2(float lo, float hi) {
    ull r; asm("mov.b64 %0, {%1,%2};" : "=l"(r) : "f"(lo), "f"(hi)); return r;
}
__device__ __forceinline__ void upk2(ull v, float& lo, float& hi) {
    asm("mov.b64 {%0,%1}, %2;" : "=f"(lo), "=f"(hi) : "l"(v));
}
__device__ __forceinline__ void fma2(ull& d, ull a, ull b) {
    asm("fma.rn.f32x2 %0, %1, %2, %0;" : "+l"(d) : "l"(a), "l"(b));
}
__device__ __forceinline__ ull mul2(ull a, ull b) {
    ull r; asm("mul.rn.f32x2 %0, %1, %2;" : "=l"(r) : "l"(a), "l"(b)); return r;
}

// ---------------------------------------------------------------------------
// C[M,N] = A[M,K] @ W[N,K]^T  — fp32 via packed FFMA2.
// Block tile 128x128, BK=16, 256 threads, 8x8 outputs per thread
// (32 f32x2 accumulators). A and W tiles stored k-major (transposed) in smem
// so the inner loop is 4x LDS.128 + 32 FFMA2 per k-step.
// ---------------------------------------------------------------------------
#define BM 128
#define BN 128
#define BK 16
#define TST 132   // transposed-tile stride (floats): %4==0, breaks conflicts

__global__ void __launch_bounds__(256)
gemm_f32x2(const float* __restrict__ A, const float* __restrict__ W,
           float* __restrict__ C, int M, int N, int K)
{
    __shared__ float AsT[BK][TST];   // AsT[k][m]
    __shared__ float WsT[BK][TST];   // WsT[k][n]

    const int tid = threadIdx.x;
    const int tx  = tid & 15, ty = tid >> 4;
    const int m0  = blockIdx.y * BM, n0 = blockIdx.x * BN;

    // loader mapping: 512 float4 per tile, 2 per thread
    const int lr = tid >> 2;          // row 0..63 (+64 for second pass)
    const int lq = (tid & 3) * 4;     // k offset within BK

    ull acc[8][4];
    #pragma unroll
    for (int i = 0; i < 8; i++)
        #pragma unroll
        for (int j = 0; j < 4; j++) acc[i][j] = 0ull;

    for (int k0 = 0; k0 < K; k0 += BK) {
        __syncthreads();
        // ---- load A tile (128x16) transposed
        #pragma unroll
        for (int p = 0; p < 2; p++) {
            int r = lr + p * 64;
            float4 v = *(const float4*)(A + (size_t)(m0 + r) * K + k0 + lq);
            AsT[lq+0][r] = v.x; AsT[lq+1][r] = v.y;
            AsT[lq+2][r] = v.z; AsT[lq+3][r] = v.w;
        }
        // ---- load W tile (128x16) transposed
        #pragma unroll
        for (int p = 0; p < 2; p++) {
            int r = lr + p * 64;
            float4 v = *(const float4*)(W + (size_t)(n0 + r) * K + k0 + lq);
            WsT[lq+0][r] = v.x; WsT[lq+1][r] = v.y;
            WsT[lq+2][r] = v.z; WsT[lq+3][r] = v.w;
        }
        __syncthreads();

        #pragma unroll
        for (int k = 0; k < BK; k++) {
            const float4 a0 = *(const float4*)(&AsT[k][ty * 8]);
            const float4 a1 = *(const float4*)(&AsT[k][ty * 8 + 4]);
            const float4 b0 = *(const float4*)(&WsT[k][tx * 8]);
            const float4 b1 = *(const float4*)(&WsT[k][tx * 8 + 4]);
            ull bb[4];
            bb[0] = pk2(b0.x, b0.y); bb[1] = pk2(b0.z, b0.w);
            bb[2] = pk2(b1.x, b1.y); bb[3] = pk2(b1.z, b1.w);
            const float av[8] = {a0.x, a0.y, a0.z, a0.w, a1.x, a1.y, a1.z, a1.w};
            #pragma unroll
            for (int i = 0; i < 8; i++) {
                const ull aa = pk2(av[i], av[i]);
                #pragma unroll
                for (int j = 0; j < 4; j++) fma2(acc[i][j], aa, bb[j]);
            }
        }
    }

    // ---- epilogue: 8 rows x 8 cols per thread, 2x STG.128 per row
    #pragma unroll
    for (int i = 0; i < 8; i++) {
        float o[8];
        #pragma unroll
        for (int j = 0; j < 4; j++) upk2(acc[i][j], o[2*j], o[2*j+1]);
        float* cp = C + (size_t)(m0 + ty * 8 + i) * N + n0 + tx * 8;
        *(float4*)(cp)     = make_float4(o[0], o[1], o[2], o[3]);
        *(float4*)(cp + 4) = make_float4(o[4], o[5], o[6], o[7]);
    }
}

// ---------------------------------------------------------------------------
// Causal flash attention (unchanged from round 6: f32x2-packed, 662us)
// ---------------------------------------------------------------------------
#define AT_STR 68
#define P_STR  65

__global__ void __launch_bounds__(256)
attn_kernel()
{
    extern __shared__ float sm[];
    float* sQT = sm;                   // [64][AT_STR] (d-major)
    float* sKT = sm + 64 * AT_STR;     // [64][AT_STR] (d-major)
    float* sP  = sm + 2 * 64 * AT_STR; // [64][P_STR]
    float* sV  = sKT;                  // V overlays K buffer

    const int tx  = threadIdx.x, ty = threadIdx.y;
    const int tid = ty * 16 + tx;
    const int qb  = (L_ / 64 - 1) - blockIdx.x;   // big tiles first
    const int b   = blockIdx.y >> 4;
    const int h   = blockIdx.y & 15;

    const size_t base = (size_t)b * L_ * D_ + (size_t)h * DH_;
    const float* Qp = g_Q + base;
    const float* Kp = g_K + base;
    const float* Vp = g_V + base;

    for (int idx = tid; idx < 64 * 64; idx += 256) {
        int r = idx >> 6, c = idx & 63;
        sQT[c * AT_STR + r] = Qp[(size_t)(qb * 64 + r) * D_ + c];
    }

    float Mx[4], Ls[4];
    ull accO[4][2];
    #pragma unroll
    for (int i = 0; i < 4; i++) {
        Mx[i] = -INFINITY; Ls[i] = 0.f;
        accO[i][0] = 0ull; accO[i][1] = 0ull;
    }

    for (int kb = 0; kb <= qb; kb++) {
        __syncthreads();
        for (int idx = tid; idx < 64 * 64; idx += 256) {
            int r = idx >> 6, c = idx & 63;
            sKT[c * AT_STR + r] = Kp[(size_t)(kb * 64 + r) * D_ + c];
        }
        __syncthreads();

        ull accS[4][2];
        #pragma unroll
        for (int i = 0; i < 4; i++) { accS[i][0] = 0ull; accS[i][1] = 0ull; }

        #pragma unroll 4
        for (int d = 0; d < 64; d++) {
            const float4 aq = *(const float4*)(sQT + d * AT_STR + ty * 4);
            const float4 kq = *(const float4*)(sKT + d * AT_STR + tx * 4);
            const ull k01 = pk2(kq.x, kq.y);
            const ull k23 = pk2(kq.z, kq.w);
            ull aa;
            aa = pk2(aq.x, aq.x); fma2(accS[0][0], aa, k01); fma2(accS[0][1], aa, k23);
            aa = pk2(aq.y, aq.y); fma2(accS[1][0], aa, k01); fma2(accS[1][1], aa, k23);
            aa = pk2(aq.z, aq.z); fma2(accS[2][0], aa, k01); fma2(accS[2][1], aa, k23);
            aa = pk2(aq.w, aq.w); fma2(accS[3][0], aa, k01); fma2(accS[3][1], aa, k23);
        }

        float S[4][4];
        #pragma unroll
        for (int i = 0; i < 4; i++) {
            upk2(accS[i][0], S[i][0], S[i][1]);
            upk2(accS[i][1], S[i][2], S[i][3]);
        }

        const bool diag = (kb == qb);
        #pragma unroll
        for (int i = 0; i < 4; i++) {
            #pragma unroll
            for (int j = 0; j < 4; j++) {
                float sv = S[i][j] * 0.125f;   // 1/sqrt(64)
                if (diag && (tx * 4 + j) > (ty * 4 + i)) sv = -INFINITY;
                S[i][j] = sv;
            }
        }

        #pragma unroll
        for (int i = 0; i < 4; i++) {
            float mx = fmaxf(fmaxf(S[i][0], S[i][1]), fmaxf(S[i][2], S[i][3]));
            #pragma unroll
            for (int o = 8; o > 0; o >>= 1)
                mx = fmaxf(mx, __shfl_xor_sync(0xffffffffu, mx, o));
            float newM = fmaxf(Mx[i], mx);
            float corr = __expf(Mx[i] - newM);   // first tile: exp(-inf)=0
            Mx[i] = newM;
            Ls[i] *= corr;
            const ull cc = pk2(corr, corr);
            accO[i][0] = mul2(accO[i][0], cc);
            accO[i][1] = mul2(accO[i][1], cc);

            float P[4], rs = 0.f;
            #pragma unroll
            for (int j = 0; j < 4; j++) {
                P[j] = __expf(S[i][j] - newM);   // masked -> 0
                rs += P[j];
            }
            #pragma unroll
            for (int o = 8; o > 0; o >>= 1)
                rs += __shfl_xor_sync(0xffffffffu, rs, o);
            Ls[i] += rs;
            #pragma unroll
            for (int j = 0; j < 4; j++)
                sP[(ty * 4 + i) * P_STR + tx * 4 + j] = P[j];
        }
        __syncthreads();

        for (int idx = tid; idx < 64 * 64; idx += 256) {
            int r = idx >> 6, c = idx & 63;
            sV[r * AT_STR + c] = Vp[(size_t)(kb * 64 + r) * D_ + c];
        }
        __syncthreads();

        #pragma unroll 4
        for (int k = 0; k < 64; k++) {
            const ull v01 = *(const ull*)(sV + k * AT_STR + tx * 4);
            const ull v23 = *(const ull*)(sV + k * AT_STR + tx * 4 + 2);
            #pragma unroll
            for (int i = 0; i < 4; i++) {
                const float p = sP[(ty * 4 + i) * P_STR + k];
                const ull pp = pk2(p, p);
                fma2(accO[i][0], pp, v01);
                fma2(accO[i][1], pp, v23);
            }
        }
    }

    float* Op = g_Ao + base;
    #pragma unroll
    for (int i = 0; i < 4; i++) {
        float o0, o1, o2, o3;
        upk2(accO[i][0], o0, o1);
        upk2(accO[i][1], o2, o3);
        float inv = 1.f / Ls[i];
        float4 o4 = make_float4(o0 * inv, o1 * inv, o2 * inv, o3 * inv);
        *(float4*)(Op + (size_t)(qb * 64 + ty * 4 + i) * D_ + tx * 4) = o4;
    }
}

// ---------------------------------------------------------------------------
extern "C" void kernel_launch(void* const* d_in, const int* in_sizes, int n_in,
                              void* d_out, int out_size)
{
    const float* x  = (const float*)d_in[0];
    // d_in[1] = mask (int32 tril) — causality applied analytically
    const float* Wq = (const float*)d_in[2];
    const float* Wk = (const float*)d_in[3];
    const float* Wv = (const float*)d_in[4];
    const float* Wo = (const float*)d_in[5];
    float* out = (float*)d_out;

    void *pQ, *pK, *pV, *pA;
    cudaGetSymbolAddress(&pQ, g_Q);
    cudaGetSymbolAddress(&pK, g_K);
    cudaGetSymbolAddress(&pV, g_V);
    cudaGetSymbolAddress(&pA, g_Ao);

    dim3 ggrd(D_ / BN, M_ / BM);   // (8, 32) = 256 CTAs
    gemm_f32x2<<<ggrd, 256>>>(x, Wq, (float*)pQ, M_, D_, D_);
    gemm_f32x2<<<ggrd, 256>>>(x, Wk, (float*)pK, M_, D_, D_);
    gemm_f32x2<<<ggrd, 256>>>(x, Wv, (float*)pV, M_, D_, D_);

    const int attn_smem = (2 * 64 * AT_STR + 64 * P_STR) * (int)sizeof(float);
    cudaFuncSetAttribute(attn_kernel,
        cudaFuncAttributeMaxDynamicSharedMemorySize, attn_smem);
    attn_kernel<<<dim3(L_ / 64, B_ * H_), dim3(16, 16), attn_smem>>>();

    gemm_f32x2<<<ggrd, 256>>>((const float*)pA, Wo, out, M_, D_, D_);
}

// round 10
// speedup vs baseline: 1.3422x; 1.0037x over previous
#include <cuda_runtime.h>
#include <math.h>
#include <stdint.h>

#define B_  2
#define L_  2048
#define D_  1024
#define H_  16
#define DH_ 64
#define M_  (B_*L_)   // 4096 rows

typedef unsigned long long ull;

// Scratch (allocation-free rule): Q, K, V, attention output. 16 MB each.
__device__ float g_Q [(size_t)M_*D_];
__device__ float g_K [(size_t)M_*D_];
__device__ float g_V [(size_t)M_*D_];
__device__ float g_Ao[(size_t)M_*D_];

// ---------------------------------------------------------------------------
// packed f32x2 helpers (FFMA2: 2 fp32 MACs per FMA-pipe slot, baseline ISA)
// ---------------------------------------------------------------------------
__device__ __forceinline__ ull pk2(float lo, float hi) {
    ull r; asm("mov.b64 %0, {%1,%2};" : "=l"(r) : "f"(lo), "f"(hi)); return r;
}
__device__ __forceinline__ void upk2(ull v, float& lo, float& hi) {
    asm("mov.b64 {%0,%1}, %2;" : "=f"(lo), "=f"(hi) : "l"(v));
}
__device__ __forceinline__ void fma2(ull& d, ull a, ull b) {
    asm("fma.rn.f32x2 %0, %1, %2, %0;" : "+l"(d) : "l"(a), "l"(b));
}
__device__ __forceinline__ ull mul2(ull a, ull b) {
    ull r; asm("mul.rn.f32x2 %0, %1, %2;" : "=l"(r) : "l"(a), "l"(b)); return r;
}

// ---------------------------------------------------------------------------
// C[M,N] = A[M,K] @ W[N,K]^T  — fp32 via packed FFMA2.
// Block tile 128x128, BK=16, 256 threads, 8x8 outputs per thread
// (32 f32x2 accumulators). A and W tiles stored k-major (transposed) in smem
// so the inner loop is 4x LDS.128 + 32 FFMA2 per k-step.
// ---------------------------------------------------------------------------
#define BM 128
#define BN 128
#define BK 16
#define TST 132   // transposed-tile stride (floats): %4==0, breaks conflicts

__global__ void __launch_bounds__(256)
gemm_f32x2(const float* __restrict__ A, const float* __restrict__ W,
           float* __restrict__ C, int M, int N, int K)
{
    __shared__ float AsT[BK][TST];   // AsT[k][m]
    __shared__ float WsT[BK][TST];   // WsT[k][n]

    const int tid = threadIdx.x;
    const int tx  = tid & 15, ty = tid >> 4;
    const int m0  = blockIdx.y * BM, n0 = blockIdx.x * BN;

    // loader mapping: 512 float4 per tile, 2 per thread
    const int lr = tid >> 2;          // row 0..63 (+64 for second pass)
    const int lq = (tid & 3) * 4;     // k offset within BK

    ull acc[8][4];
    #pragma unroll
    for (int i = 0; i < 8; i++)
        #pragma unroll
        for (int j = 0; j < 4; j++) acc[i][j] = 0ull;

    for (int k0 = 0; k0 < K; k0 += BK) {
        __syncthreads();
        // ---- load A tile (128x16) transposed
        #pragma unroll
        for (int p = 0; p < 2; p++) {
            int r = lr + p * 64;
            float4 v = *(const float4*)(A + (size_t)(m0 + r) * K + k0 + lq);
            AsT[lq+0][r] = v.x; AsT[lq+1][r] = v.y;
            AsT[lq+2][r] = v.z; AsT[lq+3][r] = v.w;
        }
        // ---- load W tile (128x16) transposed
        #pragma unroll
        for (int p = 0; p < 2; p++) {
            int r = lr + p * 64;
            float4 v = *(const float4*)(W + (size_t)(n0 + r) * K + k0 + lq);
            WsT[lq+0][r] = v.x; WsT[lq+1][r] = v.y;
            WsT[lq+2][r] = v.z; WsT[lq+3][r] = v.w;
        }
        __syncthreads();

        #pragma unroll
        for (int k = 0; k < BK; k++) {
            const float4 a0 = *(const float4*)(&AsT[k][ty * 8]);
            const float4 a1 = *(const float4*)(&AsT[k][ty * 8 + 4]);
            const float4 b0 = *(const float4*)(&WsT[k][tx * 8]);
            const float4 b1 = *(const float4*)(&WsT[k][tx * 8 + 4]);
            ull bb[4];
            bb[0] = pk2(b0.x, b0.y); bb[1] = pk2(b0.z, b0.w);
            bb[2] = pk2(b1.x, b1.y); bb[3] = pk2(b1.z, b1.w);
            const float av[8] = {a0.x, a0.y, a0.z, a0.w, a1.x, a1.y, a1.z, a1.w};
            #pragma unroll
            for (int i = 0; i < 8; i++) {
                const ull aa = pk2(av[i], av[i]);
                #pragma unroll
                for (int j = 0; j < 4; j++) fma2(acc[i][j], aa, bb[j]);
            }
        }
    }

    // ---- epilogue: 8 rows x 8 cols per thread, 2x STG.128 per row
    #pragma unroll
    for (int i = 0; i < 8; i++) {
        float o[8];
        #pragma unroll
        for (int j = 0; j < 4; j++) upk2(acc[i][j], o[2*j], o[2*j+1]);
        float* cp = C + (size_t)(m0 + ty * 8 + i) * N + n0 + tx * 8;
        *(float4*)(cp)     = make_float4(o[0], o[1], o[2], o[3]);
        *(float4*)(cp + 4) = make_float4(o[4], o[5], o[6], o[7]);
    }
}

// ---------------------------------------------------------------------------
// Causal flash attention (unchanged from round 6: f32x2-packed, 662us)
// ---------------------------------------------------------------------------
#define AT_STR 68
#define P_STR  65

__global__ void __launch_bounds__(256)
attn_kernel()
{
    extern __shared__ float sm[];
    float* sQT = sm;                   // [64][AT_STR] (d-major)
    float* sKT = sm + 64 * AT_STR;     // [64][AT_STR] (d-major)
    float* sP  = sm + 2 * 64 * AT_STR; // [64][P_STR]
    float* sV  = sKT;                  // V overlays K buffer

    const int tx  = threadIdx.x, ty = threadIdx.y;
    const int tid = ty * 16 + tx;
    const int qb  = (L_ / 64 - 1) - blockIdx.x;   // big tiles first
    const int b   = blockIdx.y >> 4;
    const int h   = blockIdx.y & 15;

    const size_t base = (size_t)b * L_ * D_ + (size_t)h * DH_;
    const float* Qp = g_Q + base;
    const float* Kp = g_K + base;
    const float* Vp = g_V + base;

    for (int idx = tid; idx < 64 * 64; idx += 256) {
        int r = idx >> 6, c = idx & 63;
        sQT[c * AT_STR + r] = Qp[(size_t)(qb * 64 + r) * D_ + c];
    }

    float Mx[4], Ls[4];
    ull accO[4][2];
    #pragma unroll
    for (int i = 0; i < 4; i++) {
        Mx[i] = -INFINITY; Ls[i] = 0.f;
        accO[i][0] = 0ull; accO[i][1] = 0ull;
    }

    for (int kb = 0; kb <= qb; kb++) {
        __syncthreads();
        for (int idx = tid; idx < 64 * 64; idx += 256) {
            int r = idx >> 6, c = idx & 63;
            sKT[c * AT_STR + r] = Kp[(size_t)(kb * 64 + r) * D_ + c];
        }
        __syncthreads();

        ull accS[4][2];
        #pragma unroll
        for (int i = 0; i < 4; i++) { accS[i][0] = 0ull; accS[i][1] = 0ull; }

        #pragma unroll 4
        for (int d = 0; d < 64; d++) {
            const float4 aq = *(const float4*)(sQT + d * AT_STR + ty * 4);
            const float4 kq = *(const float4*)(sKT + d * AT_STR + tx * 4);
            const ull k01 = pk2(kq.x, kq.y);
            const ull k23 = pk2(kq.z, kq.w);
            ull aa;
            aa = pk2(aq.x, aq.x); fma2(accS[0][0], aa, k01); fma2(accS[0][1], aa, k23);
            aa = pk2(aq.y, aq.y); fma2(accS[1][0], aa, k01); fma2(accS[1][1], aa, k23);
            aa = pk2(aq.z, aq.z); fma2(accS[2][0], aa, k01); fma2(accS[2][1], aa, k23);
            aa = pk2(aq.w, aq.w); fma2(accS[3][0], aa, k01); fma2(accS[3][1], aa, k23);
        }

        float S[4][4];
        #pragma unroll
        for (int i = 0; i < 4; i++) {
            upk2(accS[i][0], S[i][0], S[i][1]);
            upk2(accS[i][1], S[i][2], S[i][3]);
        }

        const bool diag = (kb == qb);
        #pragma unroll
        for (int i = 0; i < 4; i++) {
            #pragma unroll
            for (int j = 0; j < 4; j++) {
                float sv = S[i][j] * 0.125f;   // 1/sqrt(64)
                if (diag && (tx * 4 + j) > (ty * 4 + i)) sv = -INFINITY;
                S[i][j] = sv;
            }
        }

        #pragma unroll
        for (int i = 0; i < 4; i++) {
            float mx = fmaxf(fmaxf(S[i][0], S[i][1]), fmaxf(S[i][2], S[i][3]));
            #pragma unroll
            for (int o = 8; o > 0; o >>= 1)
                mx = fmaxf(mx, __shfl_xor_sync(0xffffffffu, mx, o));
            float newM = fmaxf(Mx[i], mx);
            float corr = __expf(Mx[i] - newM);   // first tile: exp(-inf)=0
            Mx[i] = newM;
            Ls[i] *= corr;
            const ull cc = pk2(corr, corr);
            accO[i][0] = mul2(accO[i][0], cc);
            accO[i][1] = mul2(accO[i][1], cc);

            float P[4], rs = 0.f;
            #pragma unroll
            for (int j = 0; j < 4; j++) {
                P[j] = __expf(S[i][j] - newM);   // masked -> 0
                rs += P[j];
            }
            #pragma unroll
            for (int o = 8; o > 0; o >>= 1)
                rs += __shfl_xor_sync(0xffffffffu, rs, o);
            Ls[i] += rs;
            #pragma unroll
            for (int j = 0; j < 4; j++)
                sP[(ty * 4 + i) * P_STR + tx * 4 + j] = P[j];
        }
        __syncthreads();

        for (int idx = tid; idx < 64 * 64; idx += 256) {
            int r = idx >> 6, c = idx & 63;
            sV[r * AT_STR + c] = Vp[(size_t)(kb * 64 + r) * D_ + c];
        }
        __syncthreads();

        #pragma unroll 4
        for (int k = 0; k < 64; k++) {
            const ull v01 = *(const ull*)(sV + k * AT_STR + tx * 4);
            const ull v23 = *(const ull*)(sV + k * AT_STR + tx * 4 + 2);
            #pragma unroll
            for (int i = 0; i < 4; i++) {
                const float p = sP[(ty * 4 + i) * P_STR + k];
                const ull pp = pk2(p, p);
                fma2(accO[i][0], pp, v01);
                fma2(accO[i][1], pp, v23);
            }
        }
    }

    float* Op = g_Ao + base;
    #pragma unroll
    for (int i = 0; i < 4; i++) {
        float o0, o1, o2, o3;
        upk2(accO[i][0], o0, o1);
        upk2(accO[i][1], o2, o3);
        float inv = 1.f / Ls[i];
        float4 o4 = make_float4(o0 * inv, o1 * inv, o2 * inv, o3 * inv);
        *(float4*)(Op + (size_t)(qb * 64 + ty * 4 + i) * D_ + tx * 4) = o4;
    }
}

// ---------------------------------------------------------------------------
extern "C" void kernel_launch(void* const* d_in, const int* in_sizes, int n_in,
                              void* d_out, int out_size)
{
    const float* x  = (const float*)d_in[0];
    // d_in[1] = mask (int32 tril) — causality applied analytically
    const float* Wq = (const float*)d_in[2];
    const float* Wk = (const float*)d_in[3];
    const float* Wv = (const float*)d_in[4];
    const float* Wo = (const float*)d_in[5];
    float* out = (float*)d_out;

    void *pQ, *pK, *pV, *pA;
    cudaGetSymbolAddress(&pQ, g_Q);
    cudaGetSymbolAddress(&pK, g_K);
    cudaGetSymbolAddress(&pV, g_V);
    cudaGetSymbolAddress(&pA, g_Ao);

    dim3 ggrd(D_ / BN, M_ / BM);   // (8, 32) = 256 CTAs
    gemm_f32x2<<<ggrd, 256>>>(x, Wq, (float*)pQ, M_, D_, D_);
    gemm_f32x2<<<ggrd, 256>>>(x, Wk, (float*)pK, M_, D_, D_);
    gemm_f32x2<<<ggrd, 256>>>(x, Wv, (float*)pV, M_, D_, D_);

    const int attn_smem = (2 * 64 * AT_STR + 64 * P_STR) * (int)sizeof(float);
    cudaFuncSetAttribute(attn_kernel,
        cudaFuncAttributeMaxDynamicSharedMemorySize, attn_smem);
    attn_kernel<<<dim3(L_ / 64, B_ * H_), dim3(16, 16), attn_smem>>>();

    gemm_f32x2<<<ggrd, 256>>>((const float*)pA, Wo, out, M_, D_, D_);
}